// round 13
// baseline (speedup 1.0000x reference)
#include <cuda_runtime.h>
#include <cuda_fp16.h>
#include <cstdint>

#define FDIM 128
#define MAXN 50001
#define NPAD 50176      // 392 * 128, padded node count
#define MAXE 1000000
#define AP2 68          // A pitch in uint2 (64 k-pairs + pad) -> conflict-free LDS.64
#define BP32 68         // B pitch in uint32 (64 k-pairs + pad) -> conflict-free LDS.32
#define NTILES (NPAD / 64)   // 784 m-tiles of 64 rows
#define GEMM_GRID 392        // 2 tiles per block, all resident (3 blocks/SM)

// ---------------------------------------------------------------------------
// Device scratch (allocation-free per harness rules)
__device__ unsigned int g_ctrl[1];               // [0]=dtype flag (0 => int64)
__device__ int g_row_ptr[MAXN];
__device__ uint2 g_x16[(size_t)50000 * 32];      // x in fp16, row = 32 uint2
// Aggregate, fp16 hi/lo interleaved pairs: uint2[kp] = {hi(2kp),hi(2kp+1) | lo2}
// Row = 64 uint2 = 512 bytes (hi AND lo -> same bytes as the bf16 version).
__device__ uint2 g_a[(size_t)NPAD * 64];
// W^T single fp16 k-pairs, pitch BP32: g_wt[n*BP32 + kp] = {W[2kp][n], W[2kp+1][n]}
__device__ uint32_t g_wt[FDIM * BP32];

// ---------------------------------------------------------------------------
__device__ __forceinline__ uint32_t pack_h2(float a, float b) {
    __half2 h = __float22half2_rn(make_float2(a, b));
    return *(uint32_t*)&h;
}
__device__ __forceinline__ float h1_of(float a) {
    return __half2float(__float2half_rn(a));
}

// ---------------------------------------------------------------------------
// 1) dtype detect, 512 pairs: if int64, odd words are hi(u[i])=0; if int32,
//    odd words are sorted-unique u values beyond index 0 — some are nonzero.
__global__ void detect_k(const unsigned int* __restrict__ w, int npairs) {
    unsigned int local = 0;
    for (int i = threadIdx.x; i < npairs; i += blockDim.x)
        local |= w[2 * i + 1];
    if (local) atomicOr(&g_ctrl[0], 1u);
}

// 1b) convert x -> fp16 (halves gather traffic; agg is at the LTS byte cap)
__global__ void xcvt_k(const float* __restrict__ x, int nquads) {
    const int i = blockIdx.x * blockDim.x + threadIdx.x;
    if (i < nquads) {
        const float4 v = __ldg(&((const float4*)x)[i]);
        g_x16[i] = make_uint2(pack_h2(v.x, v.y), pack_h2(v.z, v.w));
    }
}

// 2) rowptr + W prep: CSR row_ptr by binary search (u sorted), W^T fp16.
__global__ void rowptr_k(const void* __restrict__ edges,
                         const float* __restrict__ W, int E, int nN) {
    const bool is64 = (g_ctrl[0] == 0);
    const long long* e64 = (const long long*)edges;
    const int* e32 = (const int*)edges;
    const int i = blockIdx.x * blockDim.x + threadIdx.x;
    if (i <= nN) {
        if (i == nN) g_row_ptr[nN] = E;
        else {
            int lo = 0, hi = E;
            while (lo < hi) {
                int mid = (lo + hi) >> 1;
                long long um = is64 ? e64[mid] : (long long)e32[mid];
                if (um < (long long)i) lo = mid + 1; else hi = mid;
            }
            g_row_ptr[i] = lo;
        }
    }
    if (i < FDIM * (FDIM / 2)) {
        const int n = i >> 6, kp = i & 63;
        g_wt[n * BP32 + kp] = pack_h2(W[(2 * kp) * FDIM + n],
                                      W[(2 * kp + 1) * FDIM + n]);
    }
}

// ---------------------------------------------------------------------------
// 3) aggregate: static warp-per-node over fp16 x (256B/row), fp32 accum,
//    fp16 hi/lo interleaved output (A recovered exactly to ~2^-21).
template <bool IS64>
__device__ __forceinline__ void agg_body(const void* __restrict__ edges,
                                         int E, int nN) {
    const int lane = threadIdx.x & 31;
    const int gw = (blockIdx.x * blockDim.x + threadIdx.x) >> 5;
    const int nw = (gridDim.x * blockDim.x) >> 5;
    uint4* __restrict__ ga4 = (uint4*)g_a;
    const long long* __restrict__ v64 = (const long long*)edges + E;
    const int* __restrict__ v32 = (const int*)edges + E;

    for (int node = gw; node < NPAD; node += nw) {
        float4 accA = make_float4(0.f, 0.f, 0.f, 0.f);
        float4 accB = make_float4(0.f, 0.f, 0.f, 0.f);
        if (node < nN) {
            const int s = g_row_ptr[node];
            const int e = g_row_ptr[node + 1];
            int j = s;
            for (; j + 4 <= e; j += 4) {
                const int a0 = IS64 ? (int)v64[j + 0] : v32[j + 0];
                const int a1 = IS64 ? (int)v64[j + 1] : v32[j + 1];
                const int a2 = IS64 ? (int)v64[j + 2] : v32[j + 2];
                const int a3 = IS64 ? (int)v64[j + 3] : v32[j + 3];
                const uint2 x0 = __ldg(&g_x16[(size_t)a0 * 32 + lane]);
                const uint2 x1 = __ldg(&g_x16[(size_t)a1 * 32 + lane]);
                const uint2 x2 = __ldg(&g_x16[(size_t)a2 * 32 + lane]);
                const uint2 x3 = __ldg(&g_x16[(size_t)a3 * 32 + lane]);
                {
                    const float2 p0 = __half22float2(*(const __half2*)&x0.x);
                    const float2 p1 = __half22float2(*(const __half2*)&x0.y);
                    accA.x += p0.x; accA.y += p0.y; accA.z += p1.x; accA.w += p1.y;
                }
                {
                    const float2 p0 = __half22float2(*(const __half2*)&x1.x);
                    const float2 p1 = __half22float2(*(const __half2*)&x1.y);
                    accB.x += p0.x; accB.y += p0.y; accB.z += p1.x; accB.w += p1.y;
                }
                {
                    const float2 p0 = __half22float2(*(const __half2*)&x2.x);
                    const float2 p1 = __half22float2(*(const __half2*)&x2.y);
                    accA.x += p0.x; accA.y += p0.y; accA.z += p1.x; accA.w += p1.y;
                }
                {
                    const float2 p0 = __half22float2(*(const __half2*)&x3.x);
                    const float2 p1 = __half22float2(*(const __half2*)&x3.y);
                    accB.x += p0.x; accB.y += p0.y; accB.z += p1.x; accB.w += p1.y;
                }
            }
            for (; j < e; j++) {
                const int v = IS64 ? (int)v64[j] : v32[j];
                const uint2 xv = __ldg(&g_x16[(size_t)v * 32 + lane]);
                const float2 p0 = __half22float2(*(const __half2*)&xv.x);
                const float2 p1 = __half22float2(*(const __half2*)&xv.y);
                accA.x += p0.x; accA.y += p0.y; accA.z += p1.x; accA.w += p1.y;
            }
            accA.x += accB.x; accA.y += accB.y; accA.z += accB.z; accA.w += accB.w;
        }
        uint4 o;
        o.x = pack_h2(accA.x, accA.y);
        o.y = pack_h2(accA.x - h1_of(accA.x), accA.y - h1_of(accA.y));
        o.z = pack_h2(accA.z, accA.w);
        o.w = pack_h2(accA.z - h1_of(accA.z), accA.w - h1_of(accA.w));
        ga4[(size_t)node * 32 + lane] = o;
    }
}

__global__ void __launch_bounds__(256) agg_k(const void* __restrict__ edges,
                                             int E, int nN) {
    if (g_ctrl[0] == 0) agg_body<true>(edges, E, nN);
    else agg_body<false>(edges, E, nN);
}

// ---------------------------------------------------------------------------
// 4) GEMM: fp16 2-pass (A = hi+lo exact, B = single fp16), all operands in
//    smem. 392 persistent blocks (3/SM, all resident, exactly 2 tiles each).
//    Block 64M x 128N, 4 warps of 32M x 64N. Per warp-ks: 8 LDS.64 (A) +
//    16 LDS.32 (B) feed 32 HMMA (2/3 of the bf16 3-pass MMA count).
__device__ __forceinline__ void mma_f16(float* c, const uint32_t* a, const uint32_t* b) {
    asm volatile(
        "mma.sync.aligned.m16n8k16.row.col.f32.f16.f16.f32 "
        "{%0,%1,%2,%3}, {%4,%5,%6,%7}, {%8,%9}, {%0,%1,%2,%3};"
        : "+f"(c[0]), "+f"(c[1]), "+f"(c[2]), "+f"(c[3])
        : "r"(a[0]), "r"(a[1]), "r"(a[2]), "r"(a[3]), "r"(b[0]), "r"(b[1]));
}

#define SMA_U2 (64 * AP2)                       // A tile: 64 rows x AP2 uint2
#define SM_BYTES (SMA_U2 * 8 + 128 * BP32 * 4)  // 34816 + 34816 = 69632

__global__ void __launch_bounds__(128, 3) gemm_k(const float* __restrict__ bias,
                                                 float* __restrict__ out, int nN) {
    extern __shared__ __align__(16) uint2 sm[];
    uint2* __restrict__ smA = sm;
    uint32_t* __restrict__ smB = (uint32_t*)(sm + SMA_U2);
    const int tid = threadIdx.x;
    const int wid = tid >> 5, lane = tid & 31;
    const int mwarp = wid & 1, nwarp = wid >> 1;
    const int qr = lane >> 2;
    const int qc = (lane & 3) * 2;

    // Stage B once: 128 rows x 17 uint4 (272B rows, pitch preserved).
    {
        const uint4* __restrict__ src = (const uint4*)g_wt;
        uint4* __restrict__ dst = (uint4*)smB;
#pragma unroll
        for (int i = 0; i < 17; i++)
            dst[i * 128 + tid] = src[i * 128 + tid];
    }

    for (int tile = blockIdx.x; tile < NTILES; tile += GEMM_GRID) {
        // ---- stage A tile: 64 rows x 32 uint4 (512B rows), repitch 32 -> 34
        {
            const uint4* __restrict__ src =
                (const uint4*)g_a + (size_t)tile * 64 * 32;
            uint4* __restrict__ dst = (uint4*)smA;
#pragma unroll
            for (int i = 0; i < 16; i++) {
                const int idx = i * 128 + tid;     // 0..2047
                const int r = idx >> 5, c = idx & 31;
                dst[r * (AP2 / 2) + c] = src[idx];
            }
        }
        __syncthreads();

        float acc[2][8][4];
#pragma unroll
        for (int j = 0; j < 2; j++)
#pragma unroll
            for (int nt = 0; nt < 8; nt++)
#pragma unroll
                for (int q = 0; q < 4; q++) acc[j][nt][q] = 0.f;

        const int r0 = mwarp * 32 + qr;
#pragma unroll
        for (int ks = 0; ks < 8; ks++) {
            const int kp0 = ks * 8 + (lane & 3);
            const uint2 a00 = smA[r0 * AP2 + kp0];
            const uint2 a01 = smA[(r0 + 8) * AP2 + kp0];
            const uint2 a02 = smA[r0 * AP2 + kp0 + 4];
            const uint2 a03 = smA[(r0 + 8) * AP2 + kp0 + 4];
            const uint2 a10 = smA[(r0 + 16) * AP2 + kp0];
            const uint2 a11 = smA[(r0 + 24) * AP2 + kp0];
            const uint2 a12 = smA[(r0 + 16) * AP2 + kp0 + 4];
            const uint2 a13 = smA[(r0 + 24) * AP2 + kp0 + 4];
            const uint32_t ahi0[4] = {a00.x, a01.x, a02.x, a03.x};
            const uint32_t alo0[4] = {a00.y, a01.y, a02.y, a03.y};
            const uint32_t ahi1[4] = {a10.x, a11.x, a12.x, a13.x};
            const uint32_t alo1[4] = {a10.y, a11.y, a12.y, a13.y};
#pragma unroll
            for (int nt = 0; nt < 8; nt++) {
                const int brow = nwarp * 64 + nt * 8 + qr;
                const uint32_t b[2] = {smB[brow * BP32 + kp0],
                                       smB[brow * BP32 + kp0 + 4]};
                mma_f16(acc[0][nt], ahi0, b);
                mma_f16(acc[0][nt], alo0, b);
                mma_f16(acc[1][nt], ahi1, b);
                mma_f16(acc[1][nt], alo1, b);
            }
        }

        // ---- epilogue ----
#pragma unroll
        for (int j = 0; j < 2; j++) {
            const int m0 = tile * 64 + mwarp * 32 + j * 16 + qr;
#pragma unroll
            for (int nt = 0; nt < 8; nt++) {
                const int n0 = nwarp * 64 + nt * 8 + qc;
                const float2 bv = *(const float2*)&bias[n0];
                if (m0 < nN) {
                    float2 r = make_float2(acc[j][nt][0] + bv.x,
                                           acc[j][nt][1] + bv.y);
                    *(float2*)&out[(size_t)m0 * FDIM + n0] = r;
                }
                if (m0 + 8 < nN) {
                    float2 r = make_float2(acc[j][nt][2] + bv.x,
                                           acc[j][nt][3] + bv.y);
                    *(float2*)&out[(size_t)(m0 + 8) * FDIM + n0] = r;
                }
            }
        }
        __syncthreads();   // protect smA before next tile's restage
    }
}

// ---------------------------------------------------------------------------
extern "C" void kernel_launch(void* const* d_in, const int* in_sizes, int n_in,
                              void* d_out, int out_size) {
    const float* x = (const float*)d_in[0];
    const void* edges = d_in[1];
    const float* W = (const float*)d_in[2];
    const float* bias = (const float*)d_in[3];
    float* out = (float*)d_out;

    const int nN = in_sizes[0] / FDIM;
    int E = in_sizes[1] / 2;
    if (E > MAXE) E = MAXE;

    void* ctrl = nullptr;
    cudaGetSymbolAddress(&ctrl, g_ctrl);
    cudaMemsetAsync(ctrl, 0, sizeof(unsigned int));

    cudaFuncSetAttribute(gemm_k, cudaFuncAttributeMaxDynamicSharedMemorySize, SM_BYTES);

    int npairs = E < 512 ? E : 512;
    const int nquads = nN * 32;
    detect_k<<<1, 256>>>((const unsigned int*)edges, npairs);
    xcvt_k<<<(nquads + 255) / 256, 256>>>(x, nquads);
    rowptr_k<<<(nN + 256) / 256, 256>>>(edges, W, E, nN);
    agg_k<<<1184, 256>>>(edges, E, nN);
    gemm_k<<<GEMM_GRID, 128, SM_BYTES>>>(bias, out, nN);
}

// round 14
// speedup vs baseline: 1.0896x; 1.0896x over previous
#include <cuda_runtime.h>
#include <cuda_fp16.h>
#include <cstdint>

#define FDIM 128
#define MAXN 50001
#define NPAD 50176      // 392 * 128, padded node count
#define MAXE 1000000
#define AP2 68          // A pitch in uint2 (64 k-pairs + pad) -> conflict-free LDS.64
#define BP32 68         // B pitch in uint32 (64 k-pairs + pad) -> conflict-free LDS.32
#define NTILES (NPAD / 64)   // 784 m-tiles of 64 rows
#define GEMM_GRID 392        // 2 tiles per block, all resident (3 blocks/SM)

// ---------------------------------------------------------------------------
// Device scratch (allocation-free per harness rules)
__device__ int g_row_ptr[MAXN];
__device__ uint2 g_x16[(size_t)50000 * 32];      // x in fp16, row = 32 uint2
// Aggregate, fp16 hi/lo interleaved pairs: uint2[kp] = {hi(2kp),hi(2kp+1) | lo2}
__device__ uint2 g_a[(size_t)NPAD * 64];
// W^T single fp16 k-pairs, pitch BP32: g_wt[n*BP32 + kp] = {W[2kp][n], W[2kp+1][n]}
__device__ uint32_t g_wt[FDIM * BP32];

// ---------------------------------------------------------------------------
__device__ __forceinline__ uint32_t pack_h2(float a, float b) {
    __half2 h = __float22half2_rn(make_float2(a, b));
    return *(uint32_t*)&h;
}
__device__ __forceinline__ float h1_of(float a) {
    return __half2float(__float2half_rn(a));
}
__device__ __forceinline__ uint32_t smem_u32(const void* p) {
    uint32_t a;
    asm("{ .reg .u64 t; cvta.to.shared.u64 t, %1; cvt.u32.u64 %0, t; }"
        : "=r"(a) : "l"(p));
    return a;
}
__device__ __forceinline__ void cp16(uint32_t smem, const void* g) {
    asm volatile("cp.async.cg.shared.global [%0], [%1], 16;"
                 :: "r"(smem), "l"(g));
}
#define CP_COMMIT() asm volatile("cp.async.commit_group;" ::: "memory")
#define CP_WAIT0()  asm volatile("cp.async.wait_group 0;" ::: "memory")

// Per-block dtype detect (warp-collective, no global flag, no extra launch):
// int64 edges -> odd 32-bit words of the u row are hi words == 0;
// int32 edges -> odd words are sorted-unique u values up to index ~1000, nonzero.
__device__ __forceinline__ bool is_int64(const unsigned* __restrict__ w, int E) {
    const int lane = threadIdx.x & 31;
    int p0 = lane * 16;     if (p0 >= E) p0 = E - 1;
    int p1 = lane * 16 + 8; if (p1 >= E) p1 = E - 1;
    const unsigned l = w[2 * p0 + 1] | w[2 * p1 + 1];
    return !__any_sync(0xffffffffu, l != 0);
}

// ---------------------------------------------------------------------------
// 1) prep: x -> fp16, CSR row_ptr (binary search over sorted u), W^T fp16.
__global__ void prep_k(const float* __restrict__ x,
                       const void* __restrict__ edges,
                       const float* __restrict__ W, int E, int nN, int nquads) {
    const bool is64 = is_int64((const unsigned*)edges, E);
    const long long* e64 = (const long long*)edges;
    const int* e32 = (const int*)edges;
    const int i = blockIdx.x * blockDim.x + threadIdx.x;
    if (i < nquads) {
        const float4 v = __ldg(&((const float4*)x)[i]);
        g_x16[i] = make_uint2(pack_h2(v.x, v.y), pack_h2(v.z, v.w));
    }
    if (i <= nN) {
        if (i == nN) g_row_ptr[nN] = E;
        else {
            int lo = 0, hi = E;
            while (lo < hi) {
                int mid = (lo + hi) >> 1;
                long long um = is64 ? e64[mid] : (long long)e32[mid];
                if (um < (long long)i) lo = mid + 1; else hi = mid;
            }
            g_row_ptr[i] = lo;
        }
    }
    if (i < FDIM * (FDIM / 2)) {
        const int n = i >> 6, kp = i & 63;
        g_wt[n * BP32 + kp] = pack_h2(W[(2 * kp) * FDIM + n],
                                      W[(2 * kp + 1) * FDIM + n]);
    }
}

// ---------------------------------------------------------------------------
// 2) aggregate: static warp-per-node over fp16 x, fp32 accum, fp16 hi/lo out.
template <bool IS64>
__device__ __forceinline__ void agg_body(const void* __restrict__ edges,
                                         int E, int nN) {
    const int lane = threadIdx.x & 31;
    const int gw = (blockIdx.x * blockDim.x + threadIdx.x) >> 5;
    const int nw = (gridDim.x * blockDim.x) >> 5;
    uint4* __restrict__ ga4 = (uint4*)g_a;
    const long long* __restrict__ v64 = (const long long*)edges + E;
    const int* __restrict__ v32 = (const int*)edges + E;

    for (int node = gw; node < NPAD; node += nw) {
        float4 accA = make_float4(0.f, 0.f, 0.f, 0.f);
        float4 accB = make_float4(0.f, 0.f, 0.f, 0.f);
        if (node < nN) {
            const int s = g_row_ptr[node];
            const int e = g_row_ptr[node + 1];
            int j = s;
            for (; j + 4 <= e; j += 4) {
                const int a0 = IS64 ? (int)v64[j + 0] : v32[j + 0];
                const int a1 = IS64 ? (int)v64[j + 1] : v32[j + 1];
                const int a2 = IS64 ? (int)v64[j + 2] : v32[j + 2];
                const int a3 = IS64 ? (int)v64[j + 3] : v32[j + 3];
                const uint2 x0 = __ldg(&g_x16[(size_t)a0 * 32 + lane]);
                const uint2 x1 = __ldg(&g_x16[(size_t)a1 * 32 + lane]);
                const uint2 x2 = __ldg(&g_x16[(size_t)a2 * 32 + lane]);
                const uint2 x3 = __ldg(&g_x16[(size_t)a3 * 32 + lane]);
                {
                    const float2 p0 = __half22float2(*(const __half2*)&x0.x);
                    const float2 p1 = __half22float2(*(const __half2*)&x0.y);
                    accA.x += p0.x; accA.y += p0.y; accA.z += p1.x; accA.w += p1.y;
                }
                {
                    const float2 p0 = __half22float2(*(const __half2*)&x1.x);
                    const float2 p1 = __half22float2(*(const __half2*)&x1.y);
                    accB.x += p0.x; accB.y += p0.y; accB.z += p1.x; accB.w += p1.y;
                }
                {
                    const float2 p0 = __half22float2(*(const __half2*)&x2.x);
                    const float2 p1 = __half22float2(*(const __half2*)&x2.y);
                    accA.x += p0.x; accA.y += p0.y; accA.z += p1.x; accA.w += p1.y;
                }
                {
                    const float2 p0 = __half22float2(*(const __half2*)&x3.x);
                    const float2 p1 = __half22float2(*(const __half2*)&x3.y);
                    accB.x += p0.x; accB.y += p0.y; accB.z += p1.x; accB.w += p1.y;
                }
            }
            for (; j < e; j++) {
                const int v = IS64 ? (int)v64[j] : v32[j];
                const uint2 xv = __ldg(&g_x16[(size_t)v * 32 + lane]);
                const float2 p0 = __half22float2(*(const __half2*)&xv.x);
                const float2 p1 = __half22float2(*(const __half2*)&xv.y);
                accA.x += p0.x; accA.y += p0.y; accA.z += p1.x; accA.w += p1.y;
            }
            accA.x += accB.x; accA.y += accB.y; accA.z += accB.z; accA.w += accB.w;
        }
        uint4 o;
        o.x = pack_h2(accA.x, accA.y);
        o.y = pack_h2(accA.x - h1_of(accA.x), accA.y - h1_of(accA.y));
        o.z = pack_h2(accA.z, accA.w);
        o.w = pack_h2(accA.z - h1_of(accA.z), accA.w - h1_of(accA.w));
        ga4[(size_t)node * 32 + lane] = o;
    }
}

__global__ void __launch_bounds__(256) agg_k(const void* __restrict__ edges,
                                             int E, int nN) {
    if (is_int64((const unsigned*)edges, E)) agg_body<true>(edges, E, nN);
    else agg_body<false>(edges, E, nN);
}

// ---------------------------------------------------------------------------
// 3) GEMM: fp16 2-pass (A = hi+lo exact, B = single fp16), smem operands,
//    cp.async staging (fire-and-forget -> full MLP, no LDG->STS serialization).
//    392 persistent blocks (3/SM, all resident, exactly 2 tiles each).
__device__ __forceinline__ void mma_f16(float* c, const uint32_t* a, const uint32_t* b) {
    asm volatile(
        "mma.sync.aligned.m16n8k16.row.col.f32.f16.f16.f32 "
        "{%0,%1,%2,%3}, {%4,%5,%6,%7}, {%8,%9}, {%0,%1,%2,%3};"
        : "+f"(c[0]), "+f"(c[1]), "+f"(c[2]), "+f"(c[3])
        : "r"(a[0]), "r"(a[1]), "r"(a[2]), "r"(a[3]), "r"(b[0]), "r"(b[1]));
}

#define SMA_U2 (64 * AP2)                       // A tile: 64 rows x AP2 uint2
#define SM_BYTES (SMA_U2 * 8 + 128 * BP32 * 4)  // 34816 + 34816 = 69632

__global__ void __launch_bounds__(128, 3) gemm_k(const float* __restrict__ bias,
                                                 float* __restrict__ out, int nN) {
    extern __shared__ __align__(16) uint2 sm[];
    uint2* __restrict__ smA = sm;
    uint32_t* __restrict__ smB = (uint32_t*)(sm + SMA_U2);
    const uint32_t sbA = smem_u32(sm);
    const uint32_t sbB = sbA + SMA_U2 * 8;
    const int tid = threadIdx.x;
    const int wid = tid >> 5, lane = tid & 31;
    const int mwarp = wid & 1, nwarp = wid >> 1;
    const int qr = lane >> 2;
    const int qc = (lane & 3) * 2;

    // Stage B once via cp.async: 128 rows x 272B, 2176 16B-chunks.
    {
        const char* __restrict__ src = (const char*)g_wt;
#pragma unroll
        for (int i = 0; i < 17; i++) {
            const int idx = i * 128 + tid;
            cp16(sbB + idx * 16, src + (size_t)idx * 16);
        }
    }

    for (int tile = blockIdx.x; tile < NTILES; tile += GEMM_GRID) {
        // ---- stage A tile via cp.async: 64 rows x 512B, repitch 32 -> 34 ----
        {
            const char* __restrict__ src =
                (const char*)g_a + (size_t)tile * 64 * 512;
#pragma unroll
            for (int i = 0; i < 16; i++) {
                const int idx = i * 128 + tid;     // 0..2047
                const int r = idx >> 5, c = idx & 31;
                cp16(sbA + (r * 34 + c) * 16, src + (size_t)idx * 16);
            }
        }
        CP_COMMIT();
        CP_WAIT0();
        __syncthreads();

        float acc[2][8][4];
#pragma unroll
        for (int j = 0; j < 2; j++)
#pragma unroll
            for (int nt = 0; nt < 8; nt++)
#pragma unroll
                for (int q = 0; q < 4; q++) acc[j][nt][q] = 0.f;

        const int r0 = mwarp * 32 + qr;
#pragma unroll
        for (int ks = 0; ks < 8; ks++) {
            const int kp0 = ks * 8 + (lane & 3);
            const uint2 a00 = smA[r0 * AP2 + kp0];
            const uint2 a01 = smA[(r0 + 8) * AP2 + kp0];
            const uint2 a02 = smA[r0 * AP2 + kp0 + 4];
            const uint2 a03 = smA[(r0 + 8) * AP2 + kp0 + 4];
            const uint2 a10 = smA[(r0 + 16) * AP2 + kp0];
            const uint2 a11 = smA[(r0 + 24) * AP2 + kp0];
            const uint2 a12 = smA[(r0 + 16) * AP2 + kp0 + 4];
            const uint2 a13 = smA[(r0 + 24) * AP2 + kp0 + 4];
            const uint32_t ahi0[4] = {a00.x, a01.x, a02.x, a03.x};
            const uint32_t alo0[4] = {a00.y, a01.y, a02.y, a03.y};
            const uint32_t ahi1[4] = {a10.x, a11.x, a12.x, a13.x};
            const uint32_t alo1[4] = {a10.y, a11.y, a12.y, a13.y};
#pragma unroll
            for (int nt = 0; nt < 8; nt++) {
                const int brow = nwarp * 64 + nt * 8 + qr;
                const uint32_t b[2] = {smB[brow * BP32 + kp0],
                                       smB[brow * BP32 + kp0 + 4]};
                mma_f16(acc[0][nt], ahi0, b);
                mma_f16(acc[0][nt], alo0, b);
                mma_f16(acc[1][nt], ahi1, b);
                mma_f16(acc[1][nt], alo1, b);
            }
        }

        // ---- epilogue ----
#pragma unroll
        for (int j = 0; j < 2; j++) {
            const int m0 = tile * 64 + mwarp * 32 + j * 16 + qr;
#pragma unroll
            for (int nt = 0; nt < 8; nt++) {
                const int n0 = nwarp * 64 + nt * 8 + qc;
                const float2 bv = *(const float2*)&bias[n0];
                if (m0 < nN) {
                    float2 r = make_float2(acc[j][nt][0] + bv.x,
                                           acc[j][nt][1] + bv.y);
                    *(float2*)&out[(size_t)m0 * FDIM + n0] = r;
                }
                if (m0 + 8 < nN) {
                    float2 r = make_float2(acc[j][nt][2] + bv.x,
                                           acc[j][nt][3] + bv.y);
                    *(float2*)&out[(size_t)(m0 + 8) * FDIM + n0] = r;
                }
            }
        }
        __syncthreads();   // protect smA before next tile's restage
    }
}

// ---------------------------------------------------------------------------
extern "C" void kernel_launch(void* const* d_in, const int* in_sizes, int n_in,
                              void* d_out, int out_size) {
    const float* x = (const float*)d_in[0];
    const void* edges = d_in[1];
    const float* W = (const float*)d_in[2];
    const float* bias = (const float*)d_in[3];
    float* out = (float*)d_out;

    const int nN = in_sizes[0] / FDIM;
    int E = in_sizes[1] / 2;
    if (E > MAXE) E = MAXE;
    const int nquads = nN * 32;

    cudaFuncSetAttribute(gemm_k, cudaFuncAttributeMaxDynamicSharedMemorySize, SM_BYTES);

    prep_k<<<(nquads + 255) / 256, 256>>>(x, edges, W, E, nN, nquads);
    agg_k<<<1184, 256>>>(edges, E, nN);
    gemm_k<<<GEMM_GRID, 128, SM_BYTES>>>(bias, out, nN);
}

// round 15
// speedup vs baseline: 1.1726x; 1.0762x over previous
#include <cuda_runtime.h>
#include <cuda_fp16.h>
#include <cstdint>

#define FDIM 128
#define MAXN 50001
#define NPAD 50176      // 392 * 128, padded node count
#define MAXE 1000000
#define AP2 68          // A pitch in uint2 (64 k-pairs + pad) -> conflict-free LDS.64
#define BP32 68         // B pitch in uint32 (64 k-pairs + pad) -> conflict-free LDS.32
#define NTILES (NPAD / 64)   // 784 m-tiles of 64 rows
#define GEMM_GRID 392        // 2 tiles per block, all resident (3 blocks/SM)

// ---------------------------------------------------------------------------
// Device scratch (allocation-free per harness rules)
__device__ int g_row_ptr[MAXN];
__device__ uint2 g_x16[(size_t)50000 * 32];      // x in fp16, row = 32 uint2
// Aggregate, fp16 hi/lo interleaved pairs: uint2[kp] = {hi(2kp),hi(2kp+1) | lo2}
__device__ uint2 g_a[(size_t)NPAD * 64];
// W^T single fp16 k-pairs, pitch BP32: g_wt[n*BP32 + kp] = {W[2kp][n], W[2kp+1][n]}
__device__ uint32_t g_wt[FDIM * BP32];

// ---------------------------------------------------------------------------
__device__ __forceinline__ uint32_t pack_h2(float a, float b) {
    __half2 h = __float22half2_rn(make_float2(a, b));
    return *(uint32_t*)&h;
}
__device__ __forceinline__ float h1_of(float a) {
    return __half2float(__float2half_rn(a));
}
__device__ __forceinline__ uint32_t smem_u32(const void* p) {
    uint32_t a;
    asm("{ .reg .u64 t; cvta.to.shared.u64 t, %1; cvt.u32.u64 %0, t; }"
        : "=r"(a) : "l"(p));
    return a;
}
__device__ __forceinline__ void cp16(uint32_t smem, const void* g) {
    asm volatile("cp.async.cg.shared.global [%0], [%1], 16;"
                 :: "r"(smem), "l"(g));
}
#define CP_COMMIT() asm volatile("cp.async.commit_group;" ::: "memory")
#define CP_WAIT0()  asm volatile("cp.async.wait_group 0;" ::: "memory")

// Per-block dtype detect (warp-collective): int64 edges -> odd 32-bit words of
// the u row are hi words == 0; int32 -> sorted-unique u values, nonzero.
__device__ __forceinline__ bool is_int64(const unsigned* __restrict__ w, int E) {
    const int lane = threadIdx.x & 31;
    int p0 = lane * 16;     if (p0 >= E) p0 = E - 1;
    int p1 = lane * 16 + 8; if (p1 >= E) p1 = E - 1;
    const unsigned l = w[2 * p0 + 1] | w[2 * p1 + 1];
    return !__any_sync(0xffffffffu, l != 0);
}

// ---------------------------------------------------------------------------
// 1) prep: x -> fp16 (4 float4 loads / thread, MLP=4, STG.128 stores),
//    CSR row_ptr (binary search over sorted u), W^T fp16 pack.
__global__ void prep_k(const float* __restrict__ x,
                       const void* __restrict__ edges,
                       const float* __restrict__ W, int E, int nN, int ngrp) {
    const int i = blockIdx.x * blockDim.x + threadIdx.x;
    if (i < ngrp) {   // group = 4 float4 = 16 floats -> 2 uint4 fp16
        const float4* __restrict__ xs = (const float4*)x + (size_t)i * 4;
        const float4 v0 = __ldg(&xs[0]);
        const float4 v1 = __ldg(&xs[1]);
        const float4 v2 = __ldg(&xs[2]);
        const float4 v3 = __ldg(&xs[3]);
        uint4 o0, o1;
        o0.x = pack_h2(v0.x, v0.y); o0.y = pack_h2(v0.z, v0.w);
        o0.z = pack_h2(v1.x, v1.y); o0.w = pack_h2(v1.z, v1.w);
        o1.x = pack_h2(v2.x, v2.y); o1.y = pack_h2(v2.z, v2.w);
        o1.z = pack_h2(v3.x, v3.y); o1.w = pack_h2(v3.z, v3.w);
        uint4* __restrict__ dst = (uint4*)g_x16 + (size_t)i * 2;
        dst[0] = o0;
        dst[1] = o1;
    }
    if (i <= nN) {
        const bool is64 = is_int64((const unsigned*)edges, E);
        const long long* e64 = (const long long*)edges;
        const int* e32 = (const int*)edges;
        if (i == nN) g_row_ptr[nN] = E;
        else {
            int lo = 0, hi = E;
            while (lo < hi) {
                int mid = (lo + hi) >> 1;
                long long um = is64 ? e64[mid] : (long long)e32[mid];
                if (um < (long long)i) lo = mid + 1; else hi = mid;
            }
            g_row_ptr[i] = lo;
        }
    }
    if (i < FDIM * (FDIM / 2)) {
        const int n = i >> 6, kp = i & 63;
        g_wt[n * BP32 + kp] = pack_h2(W[(2 * kp) * FDIM + n],
                                      W[(2 * kp + 1) * FDIM + n]);
    }
}

// ---------------------------------------------------------------------------
// 2) aggregate: static warp-per-node over fp16 x, fp32 accum, fp16 hi/lo out.
template <bool IS64>
__device__ __forceinline__ void agg_body(const void* __restrict__ edges,
                                         int E, int nN) {
    const int lane = threadIdx.x & 31;
    const int gw = (blockIdx.x * blockDim.x + threadIdx.x) >> 5;
    const int nw = (gridDim.x * blockDim.x) >> 5;
    uint4* __restrict__ ga4 = (uint4*)g_a;
    const long long* __restrict__ v64 = (const long long*)edges + E;
    const int* __restrict__ v32 = (const int*)edges + E;

    for (int node = gw; node < NPAD; node += nw) {
        float4 accA = make_float4(0.f, 0.f, 0.f, 0.f);
        float4 accB = make_float4(0.f, 0.f, 0.f, 0.f);
        if (node < nN) {
            const int s = g_row_ptr[node];
            const int e = g_row_ptr[node + 1];
            int j = s;
            for (; j + 4 <= e; j += 4) {
                const int a0 = IS64 ? (int)v64[j + 0] : v32[j + 0];
                const int a1 = IS64 ? (int)v64[j + 1] : v32[j + 1];
                const int a2 = IS64 ? (int)v64[j + 2] : v32[j + 2];
                const int a3 = IS64 ? (int)v64[j + 3] : v32[j + 3];
                const uint2 x0 = __ldg(&g_x16[(size_t)a0 * 32 + lane]);
                const uint2 x1 = __ldg(&g_x16[(size_t)a1 * 32 + lane]);
                const uint2 x2 = __ldg(&g_x16[(size_t)a2 * 32 + lane]);
                const uint2 x3 = __ldg(&g_x16[(size_t)a3 * 32 + lane]);
                {
                    const float2 p0 = __half22float2(*(const __half2*)&x0.x);
                    const float2 p1 = __half22float2(*(const __half2*)&x0.y);
                    accA.x += p0.x; accA.y += p0.y; accA.z += p1.x; accA.w += p1.y;
                }
                {
                    const float2 p0 = __half22float2(*(const __half2*)&x1.x);
                    const float2 p1 = __half22float2(*(const __half2*)&x1.y);
                    accB.x += p0.x; accB.y += p0.y; accB.z += p1.x; accB.w += p1.y;
                }
                {
                    const float2 p0 = __half22float2(*(const __half2*)&x2.x);
                    const float2 p1 = __half22float2(*(const __half2*)&x2.y);
                    accA.x += p0.x; accA.y += p0.y; accA.z += p1.x; accA.w += p1.y;
                }
                {
                    const float2 p0 = __half22float2(*(const __half2*)&x3.x);
                    const float2 p1 = __half22float2(*(const __half2*)&x3.y);
                    accB.x += p0.x; accB.y += p0.y; accB.z += p1.x; accB.w += p1.y;
                }
            }
            for (; j < e; j++) {
                const int v = IS64 ? (int)v64[j] : v32[j];
                const uint2 xv = __ldg(&g_x16[(size_t)v * 32 + lane]);
                const float2 p0 = __half22float2(*(const __half2*)&xv.x);
                const float2 p1 = __half22float2(*(const __half2*)&xv.y);
                accA.x += p0.x; accA.y += p0.y; accA.z += p1.x; accA.w += p1.y;
            }
            accA.x += accB.x; accA.y += accB.y; accA.z += accB.z; accA.w += accB.w;
        }
        uint4 o;
        o.x = pack_h2(accA.x, accA.y);
        o.y = pack_h2(accA.x - h1_of(accA.x), accA.y - h1_of(accA.y));
        o.z = pack_h2(accA.z, accA.w);
        o.w = pack_h2(accA.z - h1_of(accA.z), accA.w - h1_of(accA.w));
        ga4[(size_t)node * 32 + lane] = o;
    }
}

__global__ void __launch_bounds__(256) agg_k(const void* __restrict__ edges,
                                             int E, int nN) {
    if (is_int64((const unsigned*)edges, E)) agg_body<true>(edges, E, nN);
    else agg_body<false>(edges, E, nN);
}

// ---------------------------------------------------------------------------
// 3) GEMM: fp16 2-pass (A = hi+lo exact, B = single fp16), smem operands,
//    cp.async staging. 392 persistent blocks (3/SM, exactly 2 tiles each).
__device__ __forceinline__ void mma_f16(float* c, const uint32_t* a, const uint32_t* b) {
    asm volatile(
        "mma.sync.aligned.m16n8k16.row.col.f32.f16.f16.f32 "
        "{%0,%1,%2,%3}, {%4,%5,%6,%7}, {%8,%9}, {%0,%1,%2,%3};"
        : "+f"(c[0]), "+f"(c[1]), "+f"(c[2]), "+f"(c[3])
        : "r"(a[0]), "r"(a[1]), "r"(a[2]), "r"(a[3]), "r"(b[0]), "r"(b[1]));
}

#define SMA_U2 (64 * AP2)                       // A tile: 64 rows x AP2 uint2
#define SM_BYTES (SMA_U2 * 8 + 128 * BP32 * 4)  // 34816 + 34816 = 69632

__global__ void __launch_bounds__(128, 3) gemm_k(const float* __restrict__ bias,
                                                 float* __restrict__ out, int nN) {
    extern __shared__ __align__(16) uint2 sm[];
    uint2* __restrict__ smA = sm;
    uint32_t* __restrict__ smB = (uint32_t*)(sm + SMA_U2);
    const uint32_t sbA = smem_u32(sm);
    const uint32_t sbB = sbA + SMA_U2 * 8;
    const int tid = threadIdx.x;
    const int wid = tid >> 5, lane = tid & 31;
    const int mwarp = wid & 1, nwarp = wid >> 1;
    const int qr = lane >> 2;
    const int qc = (lane & 3) * 2;

    // Stage B once via cp.async: 128 rows x 272B, 2176 16B-chunks.
    {
        const char* __restrict__ src = (const char*)g_wt;
#pragma unroll
        for (int i = 0; i < 17; i++) {
            const int idx = i * 128 + tid;
            cp16(sbB + idx * 16, src + (size_t)idx * 16);
        }
    }

    for (int tile = blockIdx.x; tile < NTILES; tile += GEMM_GRID) {
        // ---- stage A tile via cp.async: 64 rows x 512B, repitch 32 -> 34 ----
        {
            const char* __restrict__ src =
                (const char*)g_a + (size_t)tile * 64 * 512;
#pragma unroll
            for (int i = 0; i < 16; i++) {
                const int idx = i * 128 + tid;     // 0..2047
                const int r = idx >> 5, c = idx & 31;
                cp16(sbA + (r * 34 + c) * 16, src + (size_t)idx * 16);
            }
        }
        CP_COMMIT();
        CP_WAIT0();
        __syncthreads();

        float acc[2][8][4];
#pragma unroll
        for (int j = 0; j < 2; j++)
#pragma unroll
            for (int nt = 0; nt < 8; nt++)
#pragma unroll
                for (int q = 0; q < 4; q++) acc[j][nt][q] = 0.f;

        const int r0 = mwarp * 32 + qr;
#pragma unroll
        for (int ks = 0; ks < 8; ks++) {
            const int kp0 = ks * 8 + (lane & 3);
            const uint2 a00 = smA[r0 * AP2 + kp0];
            const uint2 a01 = smA[(r0 + 8) * AP2 + kp0];
            const uint2 a02 = smA[r0 * AP2 + kp0 + 4];
            const uint2 a03 = smA[(r0 + 8) * AP2 + kp0 + 4];
            const uint2 a10 = smA[(r0 + 16) * AP2 + kp0];
            const uint2 a11 = smA[(r0 + 24) * AP2 + kp0];
            const uint2 a12 = smA[(r0 + 16) * AP2 + kp0 + 4];
            const uint2 a13 = smA[(r0 + 24) * AP2 + kp0 + 4];
            const uint32_t ahi0[4] = {a00.x, a01.x, a02.x, a03.x};
            const uint32_t alo0[4] = {a00.y, a01.y, a02.y, a03.y};
            const uint32_t ahi1[4] = {a10.x, a11.x, a12.x, a13.x};
            const uint32_t alo1[4] = {a10.y, a11.y, a12.y, a13.y};
#pragma unroll
            for (int nt = 0; nt < 8; nt++) {
                const int brow = nwarp * 64 + nt * 8 + qr;
                const uint32_t b[2] = {smB[brow * BP32 + kp0],
                                       smB[brow * BP32 + kp0 + 4]};
                mma_f16(acc[0][nt], ahi0, b);
                mma_f16(acc[0][nt], alo0, b);
                mma_f16(acc[1][nt], ahi1, b);
                mma_f16(acc[1][nt], alo1, b);
            }
        }

        // ---- epilogue ----
#pragma unroll
        for (int j = 0; j < 2; j++) {
            const int m0 = tile * 64 + mwarp * 32 + j * 16 + qr;
#pragma unroll
            for (int nt = 0; nt < 8; nt++) {
                const int n0 = nwarp * 64 + nt * 8 + qc;
                const float2 bv = *(const float2*)&bias[n0];
                if (m0 < nN) {
                    float2 r = make_float2(acc[j][nt][0] + bv.x,
                                           acc[j][nt][1] + bv.y);
                    *(float2*)&out[(size_t)m0 * FDIM + n0] = r;
                }
                if (m0 + 8 < nN) {
                    float2 r = make_float2(acc[j][nt][2] + bv.x,
                                           acc[j][nt][3] + bv.y);
                    *(float2*)&out[(size_t)(m0 + 8) * FDIM + n0] = r;
                }
            }
        }
        __syncthreads();   // protect smA before next tile's restage
    }
}

// ---------------------------------------------------------------------------
extern "C" void kernel_launch(void* const* d_in, const int* in_sizes, int n_in,
                              void* d_out, int out_size) {
    const float* x = (const float*)d_in[0];
    const void* edges = d_in[1];
    const float* W = (const float*)d_in[2];
    const float* bias = (const float*)d_in[3];
    float* out = (float*)d_out;

    const int nN = in_sizes[0] / FDIM;
    int E = in_sizes[1] / 2;
    if (E > MAXE) E = MAXE;
    const int ngrp = nN * 8;   // groups of 16 floats

    cudaFuncSetAttribute(gemm_k, cudaFuncAttributeMaxDynamicSharedMemorySize, SM_BYTES);

    prep_k<<<(ngrp + 255) / 256, 256>>>(x, edges, W, E, nN, ngrp);
    agg_k<<<1184, 256>>>(edges, E, nN);
    gemm_k<<<GEMM_GRID, 128, SM_BYTES>>>(bias, out, nN);
}